// round 2
// baseline (speedup 1.0000x reference)
#include <cuda_runtime.h>
#include <cuda_bf16.h>
#include <cstdint>

// ============================================================================
// MaxMarginLoss on GB300 (compute_103 baseline ISA — no tcgen05 available):
// bf16 HMMA (mma.sync m16n8k16) candidate GEMM with fused streaming top-2,
// then exact fp32 rescore of the 2 candidates per row.
//   input  (4096, 512) f32
//   target (4096, 512) f32
//   veclist(50000,512) f32
//   out: scalar f32
// ============================================================================

#define EPSF 1e-8f
#define GAMMAF 0.5f

#define B_DIM 4096
#define D_DIM 512
#define V_DIM 50000
#define M_TILE 128
#define N_TILE 128
#define NUM_VT 392                 // ceil(50000/128); 392*128 = 50176
#define V_PAD (NUM_VT * N_TILE)
#define K_CHUNK 64                 // bf16 elems per stage = 128 B rows (SW128)
#define NUM_KC (D_DIM / K_CHUNK)   // 8

#define STAGE_BYTES 32768          // 16 KB A + 16 KB B
#define SMEM_TOTAL (2 * STAGE_BYTES)

// ---------------- scratch (device globals; no allocation allowed) -----------
struct Top2 { float v0; int i0; float v1; int i1; };

__device__ __align__(16) __nv_bfloat16 g_inn[(size_t)B_DIM * D_DIM];   // 4 MB
__device__ __align__(16) __nv_bfloat16 g_vnn[(size_t)V_PAD * D_DIM];   // 51 MB
__device__ float g_dpos[B_DIM];
__device__ float g_norm_in[B_DIM];
__device__ __align__(16) Top2 g_part[(size_t)NUM_VT * B_DIM];          // 25.7 MB
__device__ float g_margin[B_DIM];

// ---------------- helpers ----------------------------------------------------
#define SWZ(o) ((o) ^ (((o) >> 3) & 0x70))

__device__ __forceinline__ uint32_t smem_u32(const void* p) {
    return (uint32_t)__cvta_generic_to_shared(p);
}

__device__ __forceinline__ void cp16(uint32_t s, const void* g) {
    asm volatile("cp.async.cg.shared.global [%0], [%1], 16;" :: "r"(s), "l"(g));
}

__device__ __forceinline__ void ldmatrix_x4(uint32_t* r, uint32_t addr) {
    asm volatile("ldmatrix.sync.aligned.m8n8.x4.shared.b16 {%0,%1,%2,%3}, [%4];"
                 : "=r"(r[0]), "=r"(r[1]), "=r"(r[2]), "=r"(r[3]) : "r"(addr));
}

__device__ __forceinline__ void mma16816(float* d, const uint32_t* a,
                                         uint32_t b0, uint32_t b1) {
    asm volatile(
        "mma.sync.aligned.m16n8k16.row.col.f32.bf16.bf16.f32 "
        "{%0,%1,%2,%3}, {%4,%5,%6,%7}, {%8,%9}, {%0,%1,%2,%3};"
        : "+f"(d[0]), "+f"(d[1]), "+f"(d[2]), "+f"(d[3])
        : "r"(a[0]), "r"(a[1]), "r"(a[2]), "r"(a[3]), "r"(b0), "r"(b1));
}

__device__ __forceinline__ void top2_insert(float c, int ci,
                                            float& v0, int& i0,
                                            float& v1, int& i1) {
    if (c > v0) { v1 = v0; i1 = i0; v0 = c; i0 = ci; }
    else if (c > v1) { v1 = c; i1 = ci; }
}

// ---------------- kernel 1: normalize input rows, compute d_pos -------------
__global__ __launch_bounds__(128) void prep_input_kernel(
    const float* __restrict__ input, const float* __restrict__ target) {
    const int row = blockIdx.x;
    const int tid = threadIdx.x;

    const float4* x4 = reinterpret_cast<const float4*>(input + (size_t)row * D_DIM);
    const float4* t4 = reinterpret_cast<const float4*>(target + (size_t)row * D_DIM);
    float4 xv = x4[tid];
    float4 tv = t4[tid];
    float sxx = xv.x*xv.x + xv.y*xv.y + xv.z*xv.z + xv.w*xv.w;
    float stt = tv.x*tv.x + tv.y*tv.y + tv.z*tv.z + tv.w*tv.w;
    float sxt = xv.x*tv.x + xv.y*tv.y + xv.z*tv.z + xv.w*tv.w;

    #pragma unroll
    for (int o = 16; o > 0; o >>= 1) {
        sxx += __shfl_xor_sync(0xFFFFFFFFu, sxx, o);
        stt += __shfl_xor_sync(0xFFFFFFFFu, stt, o);
        sxt += __shfl_xor_sync(0xFFFFFFFFu, sxt, o);
    }
    __shared__ float red[12];
    const int w = tid >> 5;
    if ((tid & 31) == 0) { red[w] = sxx; red[4 + w] = stt; red[8 + w] = sxt; }
    __syncthreads();
    sxx = red[0] + red[1] + red[2] + red[3];
    stt = red[4] + red[5] + red[6] + red[7];
    sxt = red[8] + red[9] + red[10] + red[11];

    const float nx = fmaxf(sqrtf(sxx), EPSF);
    const float nt = fmaxf(sqrtf(stt), EPSF);
    const float inv = 1.0f / nx;

    __nv_bfloat162* dst = reinterpret_cast<__nv_bfloat162*>(g_inn + (size_t)row * D_DIM);
    dst[2 * tid]     = __floats2bfloat162_rn(xv.x * inv, xv.y * inv);
    dst[2 * tid + 1] = __floats2bfloat162_rn(xv.z * inv, xv.w * inv);

    if (tid == 0) {
        float sim = sxt / (nx * nt);
        g_dpos[row] = sqrtf(fmaxf(2.0f * (1.0f - sim), 1e-12f));
        g_norm_in[row] = nx;
    }
}

// ---------------- kernel 2: normalize veclist rows (bf16), zero-pad ---------
__global__ __launch_bounds__(128) void prep_vec_kernel(const float* __restrict__ veclist) {
    const int row = blockIdx.x;
    const int tid = threadIdx.x;
    __nv_bfloat162* dst = reinterpret_cast<__nv_bfloat162*>(g_vnn + (size_t)row * D_DIM);

    if (row >= V_DIM) {
        __nv_bfloat162 z = __floats2bfloat162_rn(0.0f, 0.0f);
        dst[2 * tid] = z;
        dst[2 * tid + 1] = z;
        return;
    }
    const float4* v4 = reinterpret_cast<const float4*>(veclist + (size_t)row * D_DIM);
    float4 vv = v4[tid];
    float s = vv.x*vv.x + vv.y*vv.y + vv.z*vv.z + vv.w*vv.w;
    #pragma unroll
    for (int o = 16; o > 0; o >>= 1) s += __shfl_xor_sync(0xFFFFFFFFu, s, o);
    __shared__ float red[4];
    const int w = tid >> 5;
    if ((tid & 31) == 0) red[w] = s;
    __syncthreads();
    s = red[0] + red[1] + red[2] + red[3];

    const float inv = 1.0f / fmaxf(sqrtf(s), EPSF);
    dst[2 * tid]     = __floats2bfloat162_rn(vv.x * inv, vv.y * inv);
    dst[2 * tid + 1] = __floats2bfloat162_rn(vv.z * inv, vv.w * inv);
}

// ---------------- kernel 3: bf16 HMMA GEMM + fused per-tile top-2 -----------
// Grid: (NUM_VT, B_DIM/M_TILE) = (392, 32). Block: 256 threads (8 warps).
// CTA computes D[128x128] = inn_tile @ vnn_tile^T (fp32 accum), top-2 per row.
__global__ __launch_bounds__(256, 2) void gemm_top2_kernel() {
    extern __shared__ char smem[];
    const int tid  = threadIdx.x;
    const int wid  = tid >> 5;
    const int lane = tid & 31;
    const int warp_m = wid & 3;        // 4 warps over M
    const int warp_n = wid >> 2;       // 2 warps over N
    const int m0 = warp_m * 32;
    const int n0 = warp_n * 64;
    const int mbase = blockIdx.y * M_TILE;
    const int vbase = blockIdx.x * N_TILE;

    const uint32_t sbase = smem_u32(smem);

    const __nv_bfloat16* gA = g_inn + (size_t)mbase * D_DIM;
    const __nv_bfloat16* gB = g_vnn + (size_t)vbase * D_DIM;

    // --- loaders: 128 rows x 128 B for A and for B, SW128-swizzled ---------
    auto load_stage = [&](int buf, int kc) {
        const uint32_t sA = sbase + (uint32_t)buf * STAGE_BYTES;
        const uint32_t sB = sA + 16384;
        const __nv_bfloat16* srcA = gA + kc * K_CHUNK;
        const __nv_bfloat16* srcB = gB + kc * K_CHUNK;
        #pragma unroll
        for (int t = 0; t < 4; t++) {
            int i = tid + t * 256;
            int row = i >> 3, q = i & 7;
            uint32_t off = SWZ((uint32_t)(row * 128 + q * 16));
            cp16(sA + off, srcA + (size_t)row * D_DIM + q * 8);
        }
        #pragma unroll
        for (int t = 0; t < 4; t++) {
            int i = tid + t * 256;
            int row = i >> 3, q = i & 7;
            uint32_t off = SWZ((uint32_t)(row * 128 + q * 16));
            cp16(sB + off, srcB + (size_t)row * D_DIM + q * 8);
        }
    };

    float acc[2][8][4];
    #pragma unroll
    for (int mt = 0; mt < 2; mt++)
        #pragma unroll
        for (int nt = 0; nt < 8; nt++)
            #pragma unroll
            for (int c = 0; c < 4; c++) acc[mt][nt][c] = 0.0f;

    // ldmatrix lane addressing (m8n8.x4, no trans): row = (lane&15), k-half = lane>>4
    const int lrow  = lane & 15;
    const int lkoff = (lane >> 4) * 16;

    load_stage(0, 0);
    asm volatile("cp.async.commit_group;" ::: "memory");

    for (int kc = 0; kc < NUM_KC; kc++) {
        if (kc + 1 < NUM_KC) {
            load_stage((kc + 1) & 1, kc + 1);
            asm volatile("cp.async.commit_group;" ::: "memory");
            asm volatile("cp.async.wait_group 1;" ::: "memory");
        } else {
            asm volatile("cp.async.wait_group 0;" ::: "memory");
        }
        __syncthreads();

        const uint32_t sA = sbase + (uint32_t)(kc & 1) * STAGE_BYTES;
        const uint32_t sB = sA + 16384;

        #pragma unroll
        for (int s = 0; s < 4; s++) {       // 4 k16 steps per 64-elem chunk
            uint32_t af[2][4];
            #pragma unroll
            for (int mt = 0; mt < 2; mt++) {
                uint32_t byte = (uint32_t)((m0 + mt * 16 + lrow) * 128 + s * 32 + lkoff);
                ldmatrix_x4(af[mt], sA + SWZ(byte));
            }
            #pragma unroll
            for (int p = 0; p < 4; p++) {   // 4 n16 pairs = 8 n8 tiles
                uint32_t bf[4];
                uint32_t byte = (uint32_t)((n0 + p * 16 + lrow) * 128 + s * 32 + lkoff);
                ldmatrix_x4(bf, sB + SWZ(byte));
                #pragma unroll
                for (int mt = 0; mt < 2; mt++) {
                    mma16816(acc[mt][2 * p],     af[mt], bf[0], bf[2]);
                    mma16816(acc[mt][2 * p + 1], af[mt], bf[1], bf[3]);
                }
            }
        }
        __syncthreads();
    }

    // ---- epilogue: top-2 per row over this CTA's 128-col slice -------------
    // Thread holds rows: mbase+m0+mt*16+h*8+(lane>>2), cols: vbase+n0+nt*8+2*(lane&3)+c
    Top2* stage = reinterpret_cast<Top2*>(smem);   // 128 x 2, reuse buffer

    #pragma unroll
    for (int mt = 0; mt < 2; mt++) {
        #pragma unroll
        for (int h = 0; h < 2; h++) {
            float v0 = -1e30f, v1 = -1e30f;
            int   i0 = -1, i1 = -1;
            #pragma unroll
            for (int nt = 0; nt < 8; nt++) {
                #pragma unroll
                for (int c = 0; c < 2; c++) {
                    int col = vbase + n0 + nt * 8 + 2 * (lane & 3) + c;
                    float val = acc[mt][nt][2 * h + c];
                    if (col < V_DIM) top2_insert(val, col, v0, i0, v1, i1);
                }
            }
            // merge across the 4 lanes sharing this row (lane^1, lane^2)
            #pragma unroll
            for (int o = 1; o <= 2; o <<= 1) {
                float w0 = __shfl_xor_sync(0xFFFFFFFFu, v0, o);
                int   wi0 = __shfl_xor_sync(0xFFFFFFFFu, i0, o);
                float w1 = __shfl_xor_sync(0xFFFFFFFFu, v1, o);
                int   wi1 = __shfl_xor_sync(0xFFFFFFFFu, i1, o);
                top2_insert(w0, wi0, v0, i0, v1, i1);
                top2_insert(w1, wi1, v0, i0, v1, i1);
            }
            if ((lane & 3) == 0) {
                int row_local = m0 + mt * 16 + h * 8 + (lane >> 2);
                Top2 t; t.v0 = v0; t.i0 = i0; t.v1 = v1; t.i1 = i1;
                stage[row_local * 2 + warp_n] = t;
            }
        }
    }
    __syncthreads();

    if (tid < 128) {
        Top2 a = stage[tid * 2 + 0];
        Top2 b = stage[tid * 2 + 1];
        top2_insert(b.v0, b.i0, a.v0, a.i0, a.v1, a.i1);
        top2_insert(b.v1, b.i1, a.v0, a.i0, a.v1, a.i1);
        g_part[(size_t)blockIdx.x * B_DIM + (mbase + tid)] = a;
    }
}

// ---------------- kernel 4: merge partials + exact fp32 rescore -------------
// One warp per input row; writes per-row margin (deterministic, no atomics).
__global__ __launch_bounds__(256) void reduce_rescore_kernel(
    const float* __restrict__ input, const float* __restrict__ target,
    const float* __restrict__ veclist) {
    const int warp = (int)((blockIdx.x * blockDim.x + threadIdx.x) >> 5);
    const int lane = threadIdx.x & 31;
    if (warp >= B_DIM) return;
    const int row = warp;

    float v0 = -1e30f, v1 = -1e30f;
    int   i0 = 0, i1 = 0;
    for (int s = lane; s < NUM_VT; s += 32) {
        Top2 p = g_part[(size_t)s * B_DIM + row];
        top2_insert(p.v0, p.i0, v0, i0, v1, i1);
        top2_insert(p.v1, p.i1, v0, i0, v1, i1);
    }
    #pragma unroll
    for (int o = 16; o > 0; o >>= 1) {
        float a0 = __shfl_xor_sync(0xFFFFFFFFu, v0, o);
        int   a0i = __shfl_xor_sync(0xFFFFFFFFu, i0, o);
        float a1 = __shfl_xor_sync(0xFFFFFFFFu, v1, o);
        int   a1i = __shfl_xor_sync(0xFFFFFFFFu, i1, o);
        top2_insert(a0, a0i, v0, i0, v1, i1);
        top2_insert(a1, a1i, v0, i0, v1, i1);
    }

    // exact fp32 rescore of the two candidates
    const float* x = input   + (size_t)row * D_DIM;
    const float* t = target  + (size_t)row * D_DIM;
    const float* a = veclist + (size_t)i0 * D_DIM;
    const float* b = veclist + (size_t)i1 * D_DIM;

    float d0 = 0.0f, n0 = 0.0f, d1 = 0.0f, n1 = 0.0f;
    bool eq = true;
    for (int k = lane; k < D_DIM; k += 32) {
        float xi = x[k], ai = a[k], bi = b[k], ti = t[k];
        d0 = fmaf(xi, ai, d0);
        n0 = fmaf(ai, ai, n0);
        d1 = fmaf(xi, bi, d1);
        n1 = fmaf(bi, bi, n1);
        eq = eq && (ai == ti);
    }
    #pragma unroll
    for (int o = 16; o > 0; o >>= 1) {
        d0 += __shfl_xor_sync(0xFFFFFFFFu, d0, o);
        n0 += __shfl_xor_sync(0xFFFFFFFFu, n0, o);
        d1 += __shfl_xor_sync(0xFFFFFFFFu, d1, o);
        n1 += __shfl_xor_sync(0xFFFFFFFFu, n1, o);
    }
    eq = __all_sync(0xFFFFFFFFu, eq);

    if (lane == 0) {
        const float nin = g_norm_in[row];
        const float s0 = d0 / (nin * fmaxf(sqrtf(n0), EPSF));
        const float s1 = d1 / (nin * fmaxf(sqrtf(n1), EPSF));
        const float dd0 = sqrtf(fmaxf(2.0f * (1.0f - s0), 1e-12f));
        const float dd1 = sqrtf(fmaxf(2.0f * (1.0f - s1), 1e-12f));
        const float dn = eq ? dd1 : dd0;
        const float margin = GAMMAF + g_dpos[row] - dn;
        g_margin[row] = 2.0f * fmaxf(margin, 0.0f);
    }
}

// ---------------- kernel 5: deterministic final reduction -------------------
__global__ __launch_bounds__(256) void final_sum_kernel(float* __restrict__ out) {
    __shared__ float s[256];
    float acc = 0.0f;
    for (int i = threadIdx.x; i < B_DIM; i += 256) acc += g_margin[i];
    s[threadIdx.x] = acc;
    __syncthreads();
    for (int st = 128; st > 0; st >>= 1) {
        if (threadIdx.x < st) s[threadIdx.x] += s[threadIdx.x + st];
        __syncthreads();
    }
    if (threadIdx.x == 0) out[0] = s[0] * (1.0f / (float)B_DIM);
}

// ---------------- launcher ---------------------------------------------------
extern "C" void kernel_launch(void* const* d_in, const int* in_sizes, int n_in,
                              void* d_out, int out_size) {
    (void)in_sizes; (void)n_in; (void)out_size;
    const float* input   = (const float*)d_in[0];
    const float* target  = (const float*)d_in[1];
    const float* veclist = (const float*)d_in[2];
    float* out = (float*)d_out;

    cudaFuncSetAttribute(gemm_top2_kernel,
                         cudaFuncAttributeMaxDynamicSharedMemorySize, SMEM_TOTAL);

    prep_input_kernel<<<B_DIM, 128>>>(input, target);
    prep_vec_kernel<<<V_PAD, 128>>>(veclist);

    dim3 grid(NUM_VT, B_DIM / M_TILE);
    gemm_top2_kernel<<<grid, 256, SMEM_TOTAL>>>();

    reduce_rescore_kernel<<<(B_DIM * 32) / 256, 256>>>(input, target, veclist);
    final_sum_kernel<<<1, 256>>>(out);
}